// round 10
// baseline (speedup 1.0000x reference)
#include <cuda_runtime.h>
#include <cstdint>

#define Bsz   32
#define Tt    128
#define Hh    512
#define Vv    32000
#define BLK   64

// ---------------- scratch (static __device__, no runtime alloc) ----------------
__device__ float g_ua[Bsz * Tt * Hh];          // Ua(keys) precompute  [b][t][o]
__device__ float g_h[Bsz * Hh];                // current hidden state
__device__ float g_hall[Bsz * BLK * Hh];       // all h_new, row m = b*BLK + s
__device__ float g_q[Bsz * Hh];                // Wa(h) per step
__device__ float g_gh[Bsz * 3 * Hh];           // h @ W_hh^T + b_hh
__device__ float g_gi[Bsz * 3 * Hh];           // x @ W_ih^T + b_ih
__device__ float g_ctx[Bsz * Hh];              // attention context

// ---------------- init h0 ----------------
__global__ void init_h_kernel(const float* __restrict__ eh) {
    int i = blockIdx.x * 256 + threadIdx.x;
    g_h[i] = eh[i];
}

// ---------------- generic fp32 GEMM: C[M,N] = A[M,K] * Bw[N,K]^T + bias[N] -----
// 128x128 tile, BK=8, 256 threads, 8x8 per thread.
// A_HALL: take A from g_hall; C_UA: write C to g_ua.
template <bool A_HALL, bool C_UA>
__global__ void __launch_bounds__(256)
gemm128(const float* __restrict__ Ap, const float* __restrict__ Bw,
        const float* __restrict__ bias, float* __restrict__ Cp,
        int M, int N, int K)
{
    const float* A = A_HALL ? g_hall : Ap;
    float*       C = C_UA   ? g_ua   : Cp;

    __shared__ __align__(16) float As[8][128];
    __shared__ __align__(16) float Bs[8][128];

    const int bm  = blockIdx.x * 128;     // M fastest-varying: out_w streamed once/wave
    const int bn  = blockIdx.y * 128;
    const int tid = threadIdx.x;
    const int tx  = tid & 15;
    const int ty  = tid >> 4;
    const int lrow = tid >> 1;
    const int lk   = (tid & 1) * 4;

    const float* Aptr = A  + (size_t)(bm + lrow) * K + lk;
    const float* Bptr = Bw + (size_t)(bn + lrow) * K + lk;

    float acc[8][8];
#pragma unroll
    for (int i = 0; i < 8; i++)
#pragma unroll
        for (int j = 0; j < 8; j++) acc[i][j] = 0.f;

    for (int k0 = 0; k0 < K; k0 += 8) {
        float4 av = *reinterpret_cast<const float4*>(Aptr + k0);
        float4 bv = *reinterpret_cast<const float4*>(Bptr + k0);
        __syncthreads();
        As[lk + 0][lrow] = av.x; As[lk + 1][lrow] = av.y;
        As[lk + 2][lrow] = av.z; As[lk + 3][lrow] = av.w;
        Bs[lk + 0][lrow] = bv.x; Bs[lk + 1][lrow] = bv.y;
        Bs[lk + 2][lrow] = bv.z; Bs[lk + 3][lrow] = bv.w;
        __syncthreads();
#pragma unroll
        for (int k = 0; k < 8; k++) {
            float a[8], b[8];
            *(float4*)&a[0] = *(const float4*)&As[k][ty * 8];
            *(float4*)&a[4] = *(const float4*)&As[k][ty * 8 + 4];
            *(float4*)&b[0] = *(const float4*)&Bs[k][tx * 8];
            *(float4*)&b[4] = *(const float4*)&Bs[k][tx * 8 + 4];
#pragma unroll
            for (int i = 0; i < 8; i++)
#pragma unroll
                for (int j = 0; j < 8; j++)
                    acc[i][j] = fmaf(a[i], b[j], acc[i][j]);
        }
    }

#pragma unroll
    for (int i = 0; i < 8; i++) {
        const int row = bm + ty * 8 + i;
#pragma unroll
        for (int j = 0; j < 8; j += 4) {
            const int col = bn + tx * 8 + j;
            float4 o;
            o.x = acc[i][j]     + bias[col];
            o.y = acc[i][j + 1] + bias[col + 1];
            o.z = acc[i][j + 2] + bias[col + 2];
            o.w = acc[i][j + 3] + bias[col + 3];
            *reinterpret_cast<float4*>(C + (size_t)row * N + col) = o;
        }
    }
}

// ---------------- per step: q = h@Wa^T + Wa_b ; gh = h@W_hh^T + b_hh -----------
// grid (B, 8), 256 threads; each thread one output of the 2048 (512 q + 1536 gh)
__global__ void __launch_bounds__(256)
qgh_kernel(const float* __restrict__ Wa_w, const float* __restrict__ Wa_b,
           const float* __restrict__ W_hh, const float* __restrict__ b_hh)
{
    __shared__ __align__(16) float hs[Hh];
    const int b = blockIdx.x;
    for (int i = threadIdx.x; i < Hh; i += 256) hs[i] = g_h[b * Hh + i];
    __syncthreads();

    const int o = blockIdx.y * 256 + threadIdx.x;   // [0, 2048)
    const float* wrow;
    float bb;
    float* outp;
    if (o < Hh) {
        wrow = Wa_w + (size_t)o * Hh; bb = Wa_b[o]; outp = g_q + b * Hh + o;
    } else {
        const int j = o - Hh;
        wrow = W_hh + (size_t)j * Hh; bb = b_hh[j]; outp = g_gh + b * 3 * Hh + j;
    }
    const float4* w4 = (const float4*)wrow;
    const float4* h4 = (const float4*)hs;
    float s0 = 0.f, s1 = 0.f;
#pragma unroll 8
    for (int i = 0; i < Hh / 8; i++) {
        float4 w = w4[2 * i], hv = h4[2 * i];
        s0 += w.x * hv.x + w.y * hv.y + w.z * hv.z + w.w * hv.w;
        float4 w2 = w4[2 * i + 1], hv2 = h4[2 * i + 1];
        s1 += w2.x * hv2.x + w2.y * hv2.y + w2.z * hv2.z + w2.w * hv2.w;
    }
    *outp = s0 + s1 + bb;
}

// ---------------- per step: scores + softmax + ctx (one block per b) -----------
__global__ void __launch_bounds__(256)
attn_kernel(const float* __restrict__ Va_w, const float* __restrict__ Va_b,
            const float* __restrict__ enc, float* __restrict__ attn_out, int s)
{
    __shared__ float qs[Hh];
    __shared__ float vas[Hh];
    __shared__ float sc[Tt];
    __shared__ float s_max, s_sum;

    const int b = blockIdx.x, tid = threadIdx.x;
    const int warp = tid >> 5, lane = tid & 31;

    for (int i = tid; i < Hh; i += 256) { qs[i] = g_q[b * Hh + i]; vas[i] = Va_w[i]; }
    __syncthreads();

    // scores[t] = sum_h tanh(q[h] + ua[b][t][h]) * Va[h] + Va_b
    for (int t = warp; t < Tt; t += 8) {
        const float* up = g_ua + ((size_t)b * Tt + t) * Hh;
        float acc = 0.f;
#pragma unroll 4
        for (int hh = lane; hh < Hh; hh += 32) {
            float x = qs[hh] + up[hh];
            float th;
            asm("tanh.approx.f32 %0, %1;" : "=f"(th) : "f"(x));
            acc = fmaf(th, vas[hh], acc);
        }
#pragma unroll
        for (int o = 16; o > 0; o >>= 1) acc += __shfl_xor_sync(0xffffffffu, acc, o);
        if (lane == 0) sc[t] = acc + Va_b[0];
    }
    __syncthreads();

    if (warp == 0) {
        float m = -1e30f;
        for (int t = lane; t < Tt; t += 32) m = fmaxf(m, sc[t]);
#pragma unroll
        for (int o = 16; o > 0; o >>= 1) m = fmaxf(m, __shfl_xor_sync(0xffffffffu, m, o));
        if (lane == 0) s_max = m;
    }
    __syncthreads();
    const float M = s_max;
    if (tid < Tt) sc[tid] = expf(sc[tid] - M);
    __syncthreads();
    if (warp == 0) {
        float sum = 0.f;
        for (int t = lane; t < Tt; t += 32) sum += sc[t];
#pragma unroll
        for (int o = 16; o > 0; o >>= 1) sum += __shfl_xor_sync(0xffffffffu, sum, o);
        if (lane == 0) s_sum = sum;
    }
    __syncthreads();
    const float inv = 1.0f / s_sum;
    if (tid < Tt) {
        const float w = sc[tid] * inv;
        sc[tid] = w;
        attn_out[((size_t)b * BLK + s) * Tt + tid] = w;   // attentions output
    }
    __syncthreads();

    // ctx[h] = sum_t w[t] * enc[b][t][h]
    for (int hh = tid; hh < Hh; hh += 256) {
        const float* ep = enc + (size_t)b * Tt * Hh + hh;
        float acc = 0.f;
#pragma unroll 8
        for (int t = 0; t < Tt; t++) acc = fmaf(sc[t], ep[(size_t)t * Hh], acc);
        g_ctx[b * Hh + hh] = acc;
    }
}

// ---------------- per step: gi = [emb; ctx] @ W_ih^T + b_ih --------------------
// grid (B, 6), 256 threads; one output each of the 1536
__global__ void __launch_bounds__(256)
gi_kernel(const float* __restrict__ emb, const int* __restrict__ tgt,
          const float* __restrict__ W_ih, const float* __restrict__ b_ih, int s)
{
    __shared__ __align__(16) float xs[2 * Hh];
    const int b = blockIdx.x, tid = threadIdx.x;
    const int idx = (s == 0) ? 1 : tgt[b * BLK + s - 1];   // BOS = 1, teacher forcing
    for (int i = tid; i < Hh; i += 256) {
        xs[i]      = emb[(size_t)idx * Hh + i];
        xs[Hh + i] = g_ctx[b * Hh + i];
    }
    __syncthreads();

    const int j = blockIdx.y * 256 + tid;   // [0, 1536)
    const float4* w4 = (const float4*)(W_ih + (size_t)j * 2 * Hh);
    const float4* x4 = (const float4*)xs;
    float s0 = 0.f, s1 = 0.f;
#pragma unroll 8
    for (int i = 0; i < 2 * Hh / 8; i++) {
        float4 w = w4[2 * i], x = x4[2 * i];
        s0 += w.x * x.x + w.y * x.y + w.z * x.z + w.w * x.w;
        float4 w2 = w4[2 * i + 1], x2 = x4[2 * i + 1];
        s1 += w2.x * x2.x + w2.y * x2.y + w2.z * x2.z + w2.w * x2.w;
    }
    g_gi[b * 3 * Hh + j] = s0 + s1 + b_ih[j];
}

// ---------------- per step: GRU gates + h update -------------------------------
__global__ void __launch_bounds__(256) gate_kernel(int s)
{
    const int i = blockIdx.x * 256 + threadIdx.x;   // [0, B*H)
    const int b = i >> 9;          // H = 512
    const int j = i & (Hh - 1);
    const float* gi = g_gi + b * 3 * Hh;
    const float* gh = g_gh + b * 3 * Hh;
    const float r = 1.f / (1.f + expf(-(gi[j]          + gh[j])));
    const float z = 1.f / (1.f + expf(-(gi[Hh + j]     + gh[Hh + j])));
    const float n = tanhf(gi[2 * Hh + j] + r * gh[2 * Hh + j]);
    const float hv = g_h[i];
    const float hn = (1.f - z) * n + z * hv;
    g_h[i] = hn;
    g_hall[((size_t)b * BLK + s) * Hh + j] = hn;
}

// ---------------- log_softmax in place, one block per row ----------------------
__global__ void __launch_bounds__(256) lsm_kernel(float* __restrict__ p0)
{
    float* p = p0 + (size_t)blockIdx.x * Vv;
    const int tid = threadIdx.x;
    __shared__ float red[8];
    __shared__ float bcast;

    float m = -1e30f;
    for (int i = tid; i < Vv; i += 256) m = fmaxf(m, p[i]);
#pragma unroll
    for (int o = 16; o > 0; o >>= 1) m = fmaxf(m, __shfl_xor_sync(0xffffffffu, m, o));
    if ((tid & 31) == 0) red[tid >> 5] = m;
    __syncthreads();
    if (tid == 0) {
        float mm = red[0];
        for (int w = 1; w < 8; w++) mm = fmaxf(mm, red[w]);
        bcast = mm;
    }
    __syncthreads();
    const float M = bcast;

    float sum = 0.f;
    for (int i = tid; i < Vv; i += 256) sum += expf(p[i] - M);
#pragma unroll
    for (int o = 16; o > 0; o >>= 1) sum += __shfl_xor_sync(0xffffffffu, sum, o);
    __syncthreads();                      // red[] reuse
    if ((tid & 31) == 0) red[tid >> 5] = sum;
    __syncthreads();
    if (tid == 0) {
        float ss = 0.f;
        for (int w = 0; w < 8; w++) ss += red[w];
        bcast = M + logf(ss);
    }
    __syncthreads();
    const float lse = bcast;
    for (int i = tid; i < Vv; i += 256) p[i] -= lse;
}

// ---------------- final hidden state -> output ---------------------------------
__global__ void copy_ht_kernel(float* __restrict__ hT)
{
    const int i = blockIdx.x * 256 + threadIdx.x;
    hT[i] = g_h[i];
}

// ---------------- launch --------------------------------------------------------
extern "C" void kernel_launch(void* const* d_in, const int* in_sizes, int n_in,
                              void* d_out, int out_size)
{
    const float* enc   = (const float*)d_in[0];   // [B,T,H]
    const float* eh    = (const float*)d_in[1];   // [1,B,H]
    const int*   tgt   = (const int*)  d_in[2];   // [B,BLOCK]
    const float* emb   = (const float*)d_in[3];   // [V,H]
    const float* Wa_w  = (const float*)d_in[4];
    const float* Wa_b  = (const float*)d_in[5];
    const float* Ua_w  = (const float*)d_in[6];
    const float* Ua_b  = (const float*)d_in[7];
    const float* Va_w  = (const float*)d_in[8];
    const float* Va_b  = (const float*)d_in[9];
    const float* W_ih  = (const float*)d_in[10];
    const float* W_hh  = (const float*)d_in[11];
    const float* b_ih  = (const float*)d_in[12];
    const float* b_hh  = (const float*)d_in[13];
    const float* out_w = (const float*)d_in[14];
    const float* out_b = (const float*)d_in[15];

    float* out    = (float*)d_out;
    float* logits = out;                                  // [B,BLOCK,V]
    float* hT     = out + (size_t)Bsz * BLK * Vv;         // [1,B,H]
    float* attn   = hT + (size_t)Bsz * Hh;                // [B,BLOCK,T]

    // h0 and ua_keys (independent, both precede the recurrence in stream order)
    init_h_kernel<<<Bsz * Hh / 256, 256>>>(eh);
    gemm128<false, true><<<dim3((Bsz * Tt) / 128, Hh / 128), 256>>>(
        enc, Ua_w, Ua_b, nullptr, Bsz * Tt, Hh, Hh);

    for (int s = 0; s < BLK; s++) {
        qgh_kernel<<<dim3(Bsz, 8), 256>>>(Wa_w, Wa_b, W_hh, b_hh);
        attn_kernel<<<Bsz, 256>>>(Va_w, Va_b, enc, attn, s);
        gi_kernel<<<dim3(Bsz, 6), 256>>>(emb, tgt, W_ih, b_ih, s);
        gate_kernel<<<Bsz * Hh / 256, 256>>>(s);
    }

    // batched output projection for all 64 steps, then log_softmax in place
    gemm128<true, false><<<dim3((Bsz * BLK) / 128, Vv / 128), 256>>>(
        nullptr, out_w, out_b, logits, Bsz * BLK, Vv, Hh);
    lsm_kernel<<<Bsz * BLK, 256>>>(logits);
    copy_ht_kernel<<<Bsz * Hh / 256, 256>>>(hT);
}

// round 16
// speedup vs baseline: 2.8951x; 2.8951x over previous
#include <cuda_runtime.h>
#include <cuda_bf16.h>
#include <cstdint>

#define Bsz   32
#define Tt    128
#define Hh    512
#define Vv    32000
#define BLK   64
#define Mtot  (Bsz * BLK)          // 2048

// ---------------- scratch ----------------
__device__ float g_ua[Bsz * Tt * Hh];
__device__ float g_h[Bsz * Hh];
__device__ float g_hall[Mtot * Hh];
__device__ float g_q[Bsz * Hh];
__device__ float g_gh[Bsz * 3 * Hh];
__device__ float g_gi[Bsz * 3 * Hh];
__device__ float g_ctx[Bsz * Hh];
__device__ __nv_bfloat16 g_hall_bf[Mtot * Hh];          // 2 MB
__device__ __nv_bfloat16 g_outw_bf[(size_t)Vv * Hh];    // 32.75 MB

__device__ __forceinline__ uint32_t smem_u32(const void* p) {
    uint32_t a;
    asm("{ .reg .u64 t; cvta.to.shared.u64 t, %1; cvt.u32.u64 %0, t; }" : "=r"(a) : "l"(p));
    return a;
}

// ---------------- init h0 ----------------
__global__ void init_h_kernel(const float* __restrict__ eh) {
    int i = blockIdx.x * 256 + threadIdx.x;
    g_h[i] = eh[i];
}

// ---------------- fp32 GEMM: g_ua[M,N] = enc[M,K] @ Ua_w[N,K]^T + Ua_b --------
// IMPORTANT: writes the __device__ symbol g_ua from DEVICE code (host code must
// never pass a __device__ symbol address — it resolves to the host shadow).
__global__ void __launch_bounds__(256)
ua_gemm_kernel(const float* __restrict__ A, const float* __restrict__ Bw,
               const float* __restrict__ bias)
{
    const int M = Bsz * Tt, N = Hh, K = Hh;
    float* C = g_ua;

    __shared__ __align__(16) float As[8][128];
    __shared__ __align__(16) float Bs[8][128];

    const int bm = blockIdx.x * 128;
    const int bn = blockIdx.y * 128;
    const int tid = threadIdx.x;
    const int tx = tid & 15, ty = tid >> 4;
    const int lrow = tid >> 1, lk = (tid & 1) * 4;

    const float* Aptr = A + (size_t)(bm + lrow) * K + lk;
    const float* Bptr = Bw + (size_t)(bn + lrow) * K + lk;

    float acc[8][8];
#pragma unroll
    for (int i = 0; i < 8; i++)
#pragma unroll
        for (int j = 0; j < 8; j++) acc[i][j] = 0.f;

    for (int k0 = 0; k0 < K; k0 += 8) {
        float4 av = *reinterpret_cast<const float4*>(Aptr + k0);
        float4 bv = *reinterpret_cast<const float4*>(Bptr + k0);
        __syncthreads();
        As[lk + 0][lrow] = av.x; As[lk + 1][lrow] = av.y;
        As[lk + 2][lrow] = av.z; As[lk + 3][lrow] = av.w;
        Bs[lk + 0][lrow] = bv.x; Bs[lk + 1][lrow] = bv.y;
        Bs[lk + 2][lrow] = bv.z; Bs[lk + 3][lrow] = bv.w;
        __syncthreads();
#pragma unroll
        for (int k = 0; k < 8; k++) {
            float a[8], b[8];
            *(float4*)&a[0] = *(const float4*)&As[k][ty * 8];
            *(float4*)&a[4] = *(const float4*)&As[k][ty * 8 + 4];
            *(float4*)&b[0] = *(const float4*)&Bs[k][tx * 8];
            *(float4*)&b[4] = *(const float4*)&Bs[k][tx * 8 + 4];
#pragma unroll
            for (int i = 0; i < 8; i++)
#pragma unroll
                for (int j = 0; j < 8; j++)
                    acc[i][j] = fmaf(a[i], b[j], acc[i][j]);
        }
    }
#pragma unroll
    for (int i = 0; i < 8; i++) {
        const int row = bm + ty * 8 + i;
#pragma unroll
        for (int j = 0; j < 8; j += 4) {
            const int col = bn + tx * 8 + j;
            float4 o;
            o.x = acc[i][j] + bias[col];
            o.y = acc[i][j + 1] + bias[col + 1];
            o.z = acc[i][j + 2] + bias[col + 2];
            o.w = acc[i][j + 3] + bias[col + 3];
            *reinterpret_cast<float4*>(C + (size_t)row * N + col) = o;
        }
    }
}

// ---------------- per step: q/gh, batched over ALL b ---------------------------
__global__ void __launch_bounds__(256)
qgh2_kernel(const float* __restrict__ Wa_w, const float* __restrict__ Wa_b,
            const float* __restrict__ W_hh, const float* __restrict__ b_hh)
{
    __shared__ float hs[Hh][16];
    const int tid = threadIdx.x;
    const int bg = blockIdx.y * 16;
    for (int idx = tid; idx < Hh * 16; idx += 256) {
        const int bl = idx >> 9, k = idx & (Hh - 1);
        hs[k][bl] = g_h[(bg + bl) * Hh + k];
    }
    __syncthreads();

    const int o = blockIdx.x * 16 + (tid >> 4);
    const int bl = tid & 15;
    const float* wrow;
    float bb;
    if (o < Hh) { wrow = Wa_w + (size_t)o * Hh; bb = Wa_b[o]; }
    else        { wrow = W_hh + (size_t)(o - Hh) * Hh; bb = b_hh[o - Hh]; }
    const float4* w4 = (const float4*)wrow;

    float acc = 0.f;
#pragma unroll 8
    for (int k0 = 0; k0 < Hh; k0 += 8) {
        float4 wa = w4[k0 >> 2], wb = w4[(k0 >> 2) + 1];
        acc += wa.x * hs[k0][bl] + wa.y * hs[k0 + 1][bl]
             + wa.z * hs[k0 + 2][bl] + wa.w * hs[k0 + 3][bl]
             + wb.x * hs[k0 + 4][bl] + wb.y * hs[k0 + 5][bl]
             + wb.z * hs[k0 + 6][bl] + wb.w * hs[k0 + 7][bl];
    }
    acc += bb;
    const int b = bg + bl;
    if (o < Hh) g_q[b * Hh + o] = acc;
    else        g_gh[b * 3 * Hh + (o - Hh)] = acc;
}

// ---------------- per step: scores + softmax + ctx -----------------------------
__global__ void __launch_bounds__(1024)
attn2_kernel(const float* __restrict__ Va_w, const float* __restrict__ Va_b,
             const float* __restrict__ enc, float* __restrict__ attn_out, int s)
{
    __shared__ float qs[Hh];
    __shared__ float vas[Hh];
    __shared__ float sc[Tt];
    __shared__ float cxs[2][Hh];
    __shared__ float s_max, s_sum;

    const int b = blockIdx.x, tid = threadIdx.x;
    const int warp = tid >> 5, lane = tid & 31;

    if (tid < Hh) { qs[tid] = g_q[b * Hh + tid]; vas[tid] = Va_w[tid]; }
    const float vab = Va_b[0];
    __syncthreads();

#pragma unroll
    for (int tt = 0; tt < 4; tt++) {
        const int t = warp + tt * 32;
        const float* up = g_ua + (((size_t)b * Tt + t) << 9);
        float acc = 0.f;
#pragma unroll
        for (int i = 0; i < 16; i += 4) {
            const int h0 = lane + i * 32;
            float x0 = qs[h0] + up[h0];
            float x1 = qs[h0 + 32] + up[h0 + 32];
            float x2 = qs[h0 + 64] + up[h0 + 64];
            float x3 = qs[h0 + 96] + up[h0 + 96];
            float t0, t1, t2, t3;
            asm("tanh.approx.f32 %0, %1;" : "=f"(t0) : "f"(x0));
            asm("tanh.approx.f32 %0, %1;" : "=f"(t1) : "f"(x1));
            asm("tanh.approx.f32 %0, %1;" : "=f"(t2) : "f"(x2));
            asm("tanh.approx.f32 %0, %1;" : "=f"(t3) : "f"(x3));
            acc = fmaf(t0, vas[h0], acc);
            acc = fmaf(t1, vas[h0 + 32], acc);
            acc = fmaf(t2, vas[h0 + 64], acc);
            acc = fmaf(t3, vas[h0 + 96], acc);
        }
#pragma unroll
        for (int o = 16; o > 0; o >>= 1) acc += __shfl_xor_sync(0xffffffffu, acc, o);
        if (lane == 0) sc[t] = acc + vab;
    }
    __syncthreads();

    if (warp == 0) {
        float m = fmaxf(fmaxf(sc[lane], sc[lane + 32]), fmaxf(sc[lane + 64], sc[lane + 96]));
#pragma unroll
        for (int o = 16; o > 0; o >>= 1) m = fmaxf(m, __shfl_xor_sync(0xffffffffu, m, o));
        if (lane == 0) s_max = m;
    }
    __syncthreads();
    const float M = s_max;
    if (tid < Tt) sc[tid] = expf(sc[tid] - M);
    __syncthreads();
    if (warp == 0) {
        float sum = sc[lane] + sc[lane + 32] + sc[lane + 64] + sc[lane + 96];
#pragma unroll
        for (int o = 16; o > 0; o >>= 1) sum += __shfl_xor_sync(0xffffffffu, sum, o);
        if (lane == 0) s_sum = sum;
    }
    __syncthreads();
    if (tid < Tt) {
        const float w = sc[tid] / s_sum;
        sc[tid] = w;
        attn_out[((size_t)b * BLK + s) * Tt + tid] = w;
    }
    __syncthreads();

    {
        const int hh = tid & (Hh - 1), th = tid >> 9;
        const float* ep = enc + (size_t)b * Tt * Hh + (size_t)th * 64 * Hh + hh;
        float acc = 0.f;
#pragma unroll 8
        for (int t = 0; t < 64; t++) acc = fmaf(sc[th * 64 + t], ep[(size_t)t * Hh], acc);
        cxs[th][hh] = acc;
    }
    __syncthreads();
    if (tid < Hh) g_ctx[b * Hh + tid] = cxs[0][tid] + cxs[1][tid];
}

// ---------------- per step: gi = [emb;ctx] @ W_ih^T ----------------------------
__global__ void __launch_bounds__(256)
gi2_kernel(const float* __restrict__ emb, const int* __restrict__ tgt,
           const float* __restrict__ W_ih, const float* __restrict__ b_ih, int s)
{
    __shared__ float xs[2 * Hh][8];
    const int tid = threadIdx.x;
    const int bg = blockIdx.y * 8;
    for (int idx = tid; idx < 2 * Hh * 8; idx += 256) {
        const int bl = idx >> 10, k = idx & (2 * Hh - 1);
        const int b = bg + bl;
        float v;
        if (k < Hh) {
            const int tok = (s == 0) ? 1 : tgt[b * BLK + s - 1];
            v = emb[(size_t)tok * Hh + k];
        } else {
            v = g_ctx[b * Hh + (k - Hh)];
        }
        xs[k][bl] = v;
    }
    __syncthreads();

    const int j = blockIdx.x * 32 + (tid >> 3);
    const int bl = tid & 7;
    const float4* w4 = (const float4*)(W_ih + (size_t)j * 2 * Hh);

    float acc = 0.f;
#pragma unroll 8
    for (int k0 = 0; k0 < 2 * Hh; k0 += 8) {
        float4 wa = w4[k0 >> 2], wb = w4[(k0 >> 2) + 1];
        acc += wa.x * xs[k0][bl] + wa.y * xs[k0 + 1][bl]
             + wa.z * xs[k0 + 2][bl] + wa.w * xs[k0 + 3][bl]
             + wb.x * xs[k0 + 4][bl] + wb.y * xs[k0 + 5][bl]
             + wb.z * xs[k0 + 6][bl] + wb.w * xs[k0 + 7][bl];
    }
    g_gi[(bg + bl) * 3 * Hh + j] = acc + b_ih[j];
}

// ---------------- GRU gates ----------------------------------------------------
__global__ void __launch_bounds__(256) gate_kernel(int s)
{
    const int i = blockIdx.x * 256 + threadIdx.x;
    const int b = i >> 9;
    const int j = i & (Hh - 1);
    const float* gi = g_gi + b * 3 * Hh;
    const float* gh = g_gh + b * 3 * Hh;
    const float r = 1.f / (1.f + expf(-(gi[j] + gh[j])));
    const float z = 1.f / (1.f + expf(-(gi[Hh + j] + gh[Hh + j])));
    const float n = tanhf(gi[2 * Hh + j] + r * gh[2 * Hh + j]);
    const float hv = g_h[i];
    const float hn = (1.f - z) * n + z * hv;
    g_h[i] = hn;
    g_hall[((size_t)b * BLK + s) * Hh + j] = hn;
}

// ---------------- fp32 -> bf16 converters --------------------------------------
__global__ void __launch_bounds__(256) cvt_outw_kernel(const float* __restrict__ w)
{
    const size_t i = ((size_t)blockIdx.x * 256 + threadIdx.x) * 4;
    float4 v = *reinterpret_cast<const float4*>(w + i);
    __nv_bfloat162* p = reinterpret_cast<__nv_bfloat162*>(g_outw_bf + i);
    p[0] = __floats2bfloat162_rn(v.x, v.y);
    p[1] = __floats2bfloat162_rn(v.z, v.w);
}
__global__ void __launch_bounds__(256) cvt_hall_kernel()
{
    const size_t i = ((size_t)blockIdx.x * 256 + threadIdx.x) * 4;
    float4 v = *reinterpret_cast<const float4*>(g_hall + i);
    __nv_bfloat162* p = reinterpret_cast<__nv_bfloat162*>(g_hall_bf + i);
    p[0] = __floats2bfloat162_rn(v.x, v.y);
    p[1] = __floats2bfloat162_rn(v.z, v.w);
}

// ---------------- HMMA bf16 GEMM: logits[2048,32000] = hall @ out_w^T ----------
// mma.sync m16n8k16, 128x128 block tile, BK=64, 8 warps of 64x32.
// grid.x = M tiles (16, fast) so all M-blocks share one out_w tile via L2.
__global__ void __launch_bounds__(256)
logits_mma_kernel(const float* __restrict__ bias, float* __restrict__ C)
{
    __shared__ __align__(16) __nv_bfloat16 sA[128][72];   // 72 = 64 + 8 pad (144B rows)
    __shared__ __align__(16) __nv_bfloat16 sB[128][72];

    const int tid = threadIdx.x, warp = tid >> 5, lane = tid & 31;
    const int bm = blockIdx.x * 128;
    const int bn = blockIdx.y * 128;
    const int warp_m = (warp & 1) * 64;
    const int warp_n = (warp >> 1) * 32;

    float acc[4][4][4];
#pragma unroll
    for (int mt = 0; mt < 4; mt++)
#pragma unroll
        for (int nt = 0; nt < 4; nt++)
#pragma unroll
            for (int e = 0; e < 4; e++) acc[mt][nt][e] = 0.f;

    const __nv_bfloat16* A = g_hall_bf + (size_t)bm * Hh;
    const __nv_bfloat16* B = g_outw_bf + (size_t)bn * Hh;

    const uint32_t sa0 = smem_u32(sA);
    const uint32_t sb0 = smem_u32(sB);
    // ldmatrix lane addressing (canonical sm_80 layout)
    const uint32_t aaddr = sa0 + (uint32_t)(((warp_m + (lane & 15)) * 72 + (lane >> 4) * 8) * 2);
    const uint32_t baddr = sb0 + (uint32_t)(((warp_n + (lane & 7)) * 72 + ((lane >> 3) & 1) * 8) * 2);

    const int ldrow = tid >> 3, ldcu = tid & 7;   // 8 x uint4 per 64-col row

    for (int k0 = 0; k0 < Hh; k0 += 64) {
#pragma unroll
        for (int i = 0; i < 4; i++) {
            const int row = ldrow + i * 32;
            const size_t go = (size_t)row * Hh + k0 + ldcu * 8;
            *(uint4*)(&sA[row][ldcu * 8]) = *(const uint4*)(A + go);
            *(uint4*)(&sB[row][ldcu * 8]) = *(const uint4*)(B + go);
        }
        __syncthreads();

#pragma unroll
        for (int ks = 0; ks < 4; ks++) {
            uint32_t a[4][4], b[4][2];
#pragma unroll
            for (int mt = 0; mt < 4; mt++) {
                const uint32_t ad = aaddr + (uint32_t)((mt * 16 * 72 + ks * 16) * 2);
                asm volatile("ldmatrix.sync.aligned.m8n8.x4.shared.b16 {%0,%1,%2,%3}, [%4];"
                             : "=r"(a[mt][0]), "=r"(a[mt][1]), "=r"(a[mt][2]), "=r"(a[mt][3])
                             : "r"(ad));
            }
#pragma unroll
            for (int nt = 0; nt < 4; nt++) {
                const uint32_t bd = baddr + (uint32_t)((nt * 8 * 72 + ks * 16) * 2);
                asm volatile("ldmatrix.sync.aligned.m8n8.x2.shared.b16 {%0,%1}, [%2];"
                             : "=r"(b[nt][0]), "=r"(b[nt][1]) : "r"(bd));
            }
#pragma unroll
            for (int mt = 0; mt < 4; mt++)
#pragma unroll
                for (int nt = 0; nt < 4; nt++) {
                    asm volatile(
                        "mma.sync.aligned.m16n8k16.row.col.f32.bf16.bf16.f32 "
                        "{%0,%1,%2,%3}, {%4,%5,%6,%7}, {%8,%9}, {%0,%1,%2,%3};"
                        : "+f"(acc[mt][nt][0]), "+f"(acc[mt][nt][1]),
                          "+f"(acc[mt][nt][2]), "+f"(acc[mt][nt][3])
                        : "r"(a[mt][0]), "r"(a[mt][1]), "r"(a[mt][2]), "r"(a[mt][3]),
                          "r"(b[nt][0]), "r"(b[nt][1]));
                }
        }
        __syncthreads();
    }

    // epilogue: c0,c1 -> row g, cols q*2, q*2+1 ; c2,c3 -> row g+8
    const int g = lane >> 2, q = lane & 3;
#pragma unroll
    for (int mt = 0; mt < 4; mt++) {
        const int r0 = bm + warp_m + mt * 16 + g;
#pragma unroll
        for (int nt = 0; nt < 4; nt++) {
            const int col = bn + warp_n + nt * 8 + q * 2;
            const float2 bv = *(const float2*)(bias + col);
            float2 o0, o1;
            o0.x = acc[mt][nt][0] + bv.x; o0.y = acc[mt][nt][1] + bv.y;
            o1.x = acc[mt][nt][2] + bv.x; o1.y = acc[mt][nt][3] + bv.y;
            *(float2*)(C + (size_t)r0 * Vv + col)       = o0;
            *(float2*)(C + (size_t)(r0 + 8) * Vv + col) = o1;
        }
    }
}

// ---------------- log_softmax, 512 threads + float4 ----------------------------
__global__ void __launch_bounds__(512) lsm_kernel(float* __restrict__ p0)
{
    float* p = p0 + (size_t)blockIdx.x * Vv;
    const int tid = threadIdx.x;
    __shared__ float red[16];
    __shared__ float bcast;

    float m = -1e30f;
    for (int i = tid; i < Vv / 4; i += 512) {
        float4 v = ((const float4*)p)[i];
        m = fmaxf(m, fmaxf(fmaxf(v.x, v.y), fmaxf(v.z, v.w)));
    }
#pragma unroll
    for (int o = 16; o > 0; o >>= 1) m = fmaxf(m, __shfl_xor_sync(0xffffffffu, m, o));
    if ((tid & 31) == 0) red[tid >> 5] = m;
    __syncthreads();
    if (tid == 0) {
        float mm = red[0];
        for (int w = 1; w < 16; w++) mm = fmaxf(mm, red[w]);
        bcast = mm;
    }
    __syncthreads();
    const float M = bcast;

    float sum = 0.f;
    for (int i = tid; i < Vv / 4; i += 512) {
        float4 v = ((const float4*)p)[i];
        sum += expf(v.x - M) + expf(v.y - M) + expf(v.z - M) + expf(v.w - M);
    }
#pragma unroll
    for (int o = 16; o > 0; o >>= 1) sum += __shfl_xor_sync(0xffffffffu, sum, o);
    __syncthreads();
    if ((tid & 31) == 0) red[tid >> 5] = sum;
    __syncthreads();
    if (tid == 0) {
        float ss = 0.f;
        for (int w = 0; w < 16; w++) ss += red[w];
        bcast = M + logf(ss);
    }
    __syncthreads();
    const float lse = bcast;
    for (int i = tid; i < Vv / 4; i += 512) {
        float4 v = ((const float4*)p)[i];
        v.x -= lse; v.y -= lse; v.z -= lse; v.w -= lse;
        ((float4*)p)[i] = v;
    }
}

__global__ void copy_ht_kernel(float* __restrict__ hT)
{
    const int i = blockIdx.x * 256 + threadIdx.x;
    hT[i] = g_h[i];
}

// ---------------- launch --------------------------------------------------------
extern "C" void kernel_launch(void* const* d_in, const int* in_sizes, int n_in,
                              void* d_out, int out_size)
{
    const float* enc   = (const float*)d_in[0];
    const float* eh    = (const float*)d_in[1];
    const int*   tgt   = (const int*)  d_in[2];
    const float* emb   = (const float*)d_in[3];
    const float* Wa_w  = (const float*)d_in[4];
    const float* Wa_b  = (const float*)d_in[5];
    const float* Ua_w  = (const float*)d_in[6];
    const float* Ua_b  = (const float*)d_in[7];
    const float* Va_w  = (const float*)d_in[8];
    const float* Va_b  = (const float*)d_in[9];
    const float* W_ih  = (const float*)d_in[10];
    const float* W_hh  = (const float*)d_in[11];
    const float* b_ih  = (const float*)d_in[12];
    const float* b_hh  = (const float*)d_in[13];
    const float* out_w = (const float*)d_in[14];
    const float* out_b = (const float*)d_in[15];

    float* out    = (float*)d_out;
    float* logits = out;
    float* hT     = out + (size_t)Mtot * Vv;
    float* attn   = hT + (size_t)Bsz * Hh;

    init_h_kernel<<<Bsz * Hh / 256, 256>>>(eh);
    cvt_outw_kernel<<<(int)(((size_t)Vv * Hh / 4) / 256), 256>>>(out_w);
    ua_gemm_kernel<<<dim3((Bsz * Tt) / 128, Hh / 128), 256>>>(enc, Ua_w, Ua_b);

    for (int s = 0; s < BLK; s++) {
        qgh2_kernel<<<dim3(128, 2), 256>>>(Wa_w, Wa_b, W_hh, b_hh);
        attn2_kernel<<<Bsz, 1024>>>(Va_w, Va_b, enc, attn, s);
        gi2_kernel<<<dim3(48, 4), 256>>>(emb, tgt, W_ih, b_ih, s);
        gate_kernel<<<Bsz * Hh / 256, 256>>>(s);
    }

    cvt_hall_kernel<<<(Mtot * Hh / 4) / 256, 256>>>();
    logits_mma_kernel<<<dim3(Mtot / 128, Vv / 128), 256>>>(out_b, logits);
    lsm_kernel<<<Mtot, 512>>>(logits);
    copy_ht_kernel<<<Bsz * Hh / 256, 256>>>(hT);
}

// round 17
// speedup vs baseline: 3.1645x; 1.0930x over previous
#include <cuda_runtime.h>
#include <cuda_bf16.h>
#include <cstdint>

#define Bsz   32
#define Tt    128
#define Hh    512
#define Vv    32000
#define BLK   64
#define Mtot  (Bsz * BLK)          // 2048

// ---------------- scratch ----------------
__device__ float g_ua[Bsz * Tt * Hh];
__device__ float g_h[Bsz * Hh];
__device__ float g_hall[Mtot * Hh];
__device__ float g_qp[2][Bsz * Hh];           // K-split partials of Wa(h)
__device__ float g_ghp[2][Bsz * 3 * Hh];      // K-split partials of W_hh(h)
__device__ float g_gip[2][Bsz * 3 * Hh];      // kz0: emb part, kz1: ctx part
__device__ float g_ctx[Bsz * Hh];
__device__ __nv_bfloat16 g_hall_bf[Mtot * Hh];          // 2 MB
__device__ __nv_bfloat16 g_outw_bf[(size_t)Vv * Hh];    // 32.75 MB

__device__ __forceinline__ uint32_t smem_u32(const void* p) {
    uint32_t a;
    asm("{ .reg .u64 t; cvta.to.shared.u64 t, %1; cvt.u32.u64 %0, t; }" : "=r"(a) : "l"(p));
    return a;
}

// ---------------- init h0 ----------------
__global__ void init_h_kernel(const float* __restrict__ eh) {
    int i = blockIdx.x * 256 + threadIdx.x;
    g_h[i] = eh[i];
}

// ---------------- fp32 GEMM: g_ua = enc @ Ua_w^T + Ua_b (device-symbol C) -----
__global__ void __launch_bounds__(256)
ua_gemm_kernel(const float* __restrict__ A, const float* __restrict__ Bw,
               const float* __restrict__ bias)
{
    const int N = Hh, K = Hh;
    float* C = g_ua;

    __shared__ __align__(16) float As[8][128];
    __shared__ __align__(16) float Bs[8][128];

    const int bm = blockIdx.x * 128;
    const int bn = blockIdx.y * 128;
    const int tid = threadIdx.x;
    const int tx = tid & 15, ty = tid >> 4;
    const int lrow = tid >> 1, lk = (tid & 1) * 4;

    const float* Aptr = A + (size_t)(bm + lrow) * K + lk;
    const float* Bptr = Bw + (size_t)(bn + lrow) * K + lk;

    float acc[8][8];
#pragma unroll
    for (int i = 0; i < 8; i++)
#pragma unroll
        for (int j = 0; j < 8; j++) acc[i][j] = 0.f;

    for (int k0 = 0; k0 < K; k0 += 8) {
        float4 av = *reinterpret_cast<const float4*>(Aptr + k0);
        float4 bv = *reinterpret_cast<const float4*>(Bptr + k0);
        __syncthreads();
        As[lk + 0][lrow] = av.x; As[lk + 1][lrow] = av.y;
        As[lk + 2][lrow] = av.z; As[lk + 3][lrow] = av.w;
        Bs[lk + 0][lrow] = bv.x; Bs[lk + 1][lrow] = bv.y;
        Bs[lk + 2][lrow] = bv.z; Bs[lk + 3][lrow] = bv.w;
        __syncthreads();
#pragma unroll
        for (int k = 0; k < 8; k++) {
            float a[8], b[8];
            *(float4*)&a[0] = *(const float4*)&As[k][ty * 8];
            *(float4*)&a[4] = *(const float4*)&As[k][ty * 8 + 4];
            *(float4*)&b[0] = *(const float4*)&Bs[k][tx * 8];
            *(float4*)&b[4] = *(const float4*)&Bs[k][tx * 8 + 4];
#pragma unroll
            for (int i = 0; i < 8; i++)
#pragma unroll
                for (int j = 0; j < 8; j++)
                    acc[i][j] = fmaf(a[i], b[j], acc[i][j]);
        }
    }
#pragma unroll
    for (int i = 0; i < 8; i++) {
        const int row = bm + ty * 8 + i;
#pragma unroll
        for (int j = 0; j < 8; j += 4) {
            const int col = bn + tx * 8 + j;
            float4 o;
            o.x = acc[i][j] + bias[col];
            o.y = acc[i][j + 1] + bias[col + 1];
            o.z = acc[i][j + 2] + bias[col + 2];
            o.w = acc[i][j + 3] + bias[col + 3];
            *reinterpret_cast<float4*>(C + (size_t)row * N + col) = o;
        }
    }
}

// ---------------- per step: q/gh partials, K-split x2 --------------------------
// grid (64, 4, 2), 256 thr = 32 o x 8 b. kz selects K half [kz*256, kz*256+256).
__global__ void __launch_bounds__(256)
qgh3_kernel(const float* __restrict__ Wa_w, const float* __restrict__ Wa_b,
            const float* __restrict__ W_hh, const float* __restrict__ b_hh)
{
    __shared__ float hs[256][8];   // 8 KB
    const int tid = threadIdx.x;
    const int bg = blockIdx.y * 8;
    const int kz = blockIdx.z;
    const int kbase = kz * 256;

    for (int idx = tid; idx < 256 * 8; idx += 256) {
        const int bl = idx >> 8, k = idx & 255;
        hs[k][bl] = g_h[(bg + bl) * Hh + kbase + k];
    }
    __syncthreads();

    const int o = blockIdx.x * 32 + (tid >> 3);   // [0, 2048)
    const int bl = tid & 7;
    const float* wrow;
    float bb;
    if (o < Hh) { wrow = Wa_w + (size_t)o * Hh + kbase; bb = Wa_b[o]; }
    else        { wrow = W_hh + (size_t)(o - Hh) * Hh + kbase; bb = b_hh[o - Hh]; }
    const float4* w4 = (const float4*)wrow;

    float a0 = 0.f, a1 = 0.f;
#pragma unroll 4
    for (int k0 = 0; k0 < 256; k0 += 8) {
        float4 wa = w4[k0 >> 2], wb = w4[(k0 >> 2) + 1];
        a0 += wa.x * hs[k0][bl] + wa.y * hs[k0 + 1][bl]
            + wa.z * hs[k0 + 2][bl] + wa.w * hs[k0 + 3][bl];
        a1 += wb.x * hs[k0 + 4][bl] + wb.y * hs[k0 + 5][bl]
            + wb.z * hs[k0 + 6][bl] + wb.w * hs[k0 + 7][bl];
    }
    float acc = a0 + a1;
    if (kz == 0) acc += bb;                        // bias in partial 0 only
    const int b = bg + bl;
    if (o < Hh) g_qp[kz][b * Hh + o] = acc;
    else        g_ghp[kz][b * 3 * Hh + (o - Hh)] = acc;
}

// ---------------- per step: scores + softmax + ctx -----------------------------
__global__ void __launch_bounds__(1024)
attn2_kernel(const float* __restrict__ Va_w, const float* __restrict__ Va_b,
             const float* __restrict__ enc, float* __restrict__ attn_out, int s)
{
    __shared__ float qs[Hh];
    __shared__ float vas[Hh];
    __shared__ float sc[Tt];
    __shared__ float cxs[2][Hh];
    __shared__ float s_max, s_sum;

    const int b = blockIdx.x, tid = threadIdx.x;
    const int warp = tid >> 5, lane = tid & 31;

    if (tid < Hh) {
        qs[tid] = g_qp[0][b * Hh + tid] + g_qp[1][b * Hh + tid];
        vas[tid] = Va_w[tid];
    }
    const float vab = Va_b[0];
    __syncthreads();

#pragma unroll
    for (int tt = 0; tt < 4; tt++) {
        const int t = warp + tt * 32;
        const float* up = g_ua + (((size_t)b * Tt + t) << 9);
        float acc = 0.f;
#pragma unroll
        for (int i = 0; i < 16; i += 4) {
            const int h0 = lane + i * 32;
            float x0 = qs[h0] + up[h0];
            float x1 = qs[h0 + 32] + up[h0 + 32];
            float x2 = qs[h0 + 64] + up[h0 + 64];
            float x3 = qs[h0 + 96] + up[h0 + 96];
            float t0, t1, t2, t3;
            asm("tanh.approx.f32 %0, %1;" : "=f"(t0) : "f"(x0));
            asm("tanh.approx.f32 %0, %1;" : "=f"(t1) : "f"(x1));
            asm("tanh.approx.f32 %0, %1;" : "=f"(t2) : "f"(x2));
            asm("tanh.approx.f32 %0, %1;" : "=f"(t3) : "f"(x3));
            acc = fmaf(t0, vas[h0], acc);
            acc = fmaf(t1, vas[h0 + 32], acc);
            acc = fmaf(t2, vas[h0 + 64], acc);
            acc = fmaf(t3, vas[h0 + 96], acc);
        }
#pragma unroll
        for (int o = 16; o > 0; o >>= 1) acc += __shfl_xor_sync(0xffffffffu, acc, o);
        if (lane == 0) sc[t] = acc + vab;
    }
    __syncthreads();

    if (warp == 0) {
        float m = fmaxf(fmaxf(sc[lane], sc[lane + 32]), fmaxf(sc[lane + 64], sc[lane + 96]));
#pragma unroll
        for (int o = 16; o > 0; o >>= 1) m = fmaxf(m, __shfl_xor_sync(0xffffffffu, m, o));
        if (lane == 0) s_max = m;
    }
    __syncthreads();
    const float M = s_max;
    if (tid < Tt) sc[tid] = expf(sc[tid] - M);
    __syncthreads();
    if (warp == 0) {
        float sum = sc[lane] + sc[lane + 32] + sc[lane + 64] + sc[lane + 96];
#pragma unroll
        for (int o = 16; o > 0; o >>= 1) sum += __shfl_xor_sync(0xffffffffu, sum, o);
        if (lane == 0) s_sum = sum;
    }
    __syncthreads();
    if (tid < Tt) {
        const float w = sc[tid] / s_sum;
        sc[tid] = w;
        attn_out[((size_t)b * BLK + s) * Tt + tid] = w;
    }
    __syncthreads();

    {
        const int hh = tid & (Hh - 1), th = tid >> 9;
        const float* ep = enc + (size_t)b * Tt * Hh + (size_t)th * 64 * Hh + hh;
        float acc = 0.f;
#pragma unroll 8
        for (int t = 0; t < 64; t++) acc = fmaf(sc[th * 64 + t], ep[(size_t)t * Hh], acc);
        cxs[th][hh] = acc;
    }
    __syncthreads();
    if (tid < Hh) g_ctx[b * Hh + tid] = cxs[0][tid] + cxs[1][tid];
}

// ---------------- per step: gi partials, K-split on emb/ctx boundary -----------
// grid (48, 4, 2), 256 thr = 32 j x 8 b. kz=0: emb half, kz=1: ctx half.
__global__ void __launch_bounds__(256)
gi3_kernel(const float* __restrict__ emb, const int* __restrict__ tgt,
           const float* __restrict__ W_ih, const float* __restrict__ b_ih, int s)
{
    __shared__ float xs[512][8];   // 16 KB
    const int tid = threadIdx.x;
    const int bg = blockIdx.y * 8;
    const int kz = blockIdx.z;

    for (int idx = tid; idx < 512 * 8; idx += 256) {
        const int bl = idx >> 9, k = idx & 511;
        const int b = bg + bl;
        float v;
        if (kz == 0) {
            const int tok = (s == 0) ? 1 : tgt[b * BLK + s - 1];
            v = emb[(size_t)tok * Hh + k];
        } else {
            v = g_ctx[b * Hh + k];
        }
        xs[k][bl] = v;
    }
    __syncthreads();

    const int j = blockIdx.x * 32 + (tid >> 3);   // [0, 1536)
    const int bl = tid & 7;
    const float4* w4 = (const float4*)(W_ih + (size_t)j * 2 * Hh + kz * Hh);

    float a0 = 0.f, a1 = 0.f;
#pragma unroll 4
    for (int k0 = 0; k0 < 512; k0 += 8) {
        float4 wa = w4[k0 >> 2], wb = w4[(k0 >> 2) + 1];
        a0 += wa.x * xs[k0][bl] + wa.y * xs[k0 + 1][bl]
            + wa.z * xs[k0 + 2][bl] + wa.w * xs[k0 + 3][bl];
        a1 += wb.x * xs[k0 + 4][bl] + wb.y * xs[k0 + 5][bl]
            + wb.z * xs[k0 + 6][bl] + wb.w * xs[k0 + 7][bl];
    }
    float acc = a0 + a1;
    if (kz == 0) acc += b_ih[j];
    g_gip[kz][(bg + bl) * 3 * Hh + j] = acc;
}

// ---------------- GRU gates (sums the K-split partials) ------------------------
__global__ void __launch_bounds__(256) gate_kernel(int s)
{
    const int i = blockIdx.x * 256 + threadIdx.x;
    const int b = i >> 9;
    const int j = i & (Hh - 1);
    const int base = b * 3 * Hh;
    const float gir = g_gip[0][base + j]          + g_gip[1][base + j];
    const float giz = g_gip[0][base + Hh + j]     + g_gip[1][base + Hh + j];
    const float gin = g_gip[0][base + 2 * Hh + j] + g_gip[1][base + 2 * Hh + j];
    const float ghr = g_ghp[0][base + j]          + g_ghp[1][base + j];
    const float ghz = g_ghp[0][base + Hh + j]     + g_ghp[1][base + Hh + j];
    const float ghn = g_ghp[0][base + 2 * Hh + j] + g_ghp[1][base + 2 * Hh + j];
    const float r = 1.f / (1.f + expf(-(gir + ghr)));
    const float z = 1.f / (1.f + expf(-(giz + ghz)));
    const float n = tanhf(gin + r * ghn);
    const float hv = g_h[i];
    const float hn = (1.f - z) * n + z * hv;
    g_h[i] = hn;
    g_hall[((size_t)b * BLK + s) * Hh + j] = hn;
}

// ---------------- fp32 -> bf16 converters --------------------------------------
__global__ void __launch_bounds__(256) cvt_outw_kernel(const float* __restrict__ w)
{
    const size_t i = ((size_t)blockIdx.x * 256 + threadIdx.x) * 4;
    float4 v = *reinterpret_cast<const float4*>(w + i);
    __nv_bfloat162* p = reinterpret_cast<__nv_bfloat162*>(g_outw_bf + i);
    p[0] = __floats2bfloat162_rn(v.x, v.y);
    p[1] = __floats2bfloat162_rn(v.z, v.w);
}
__global__ void __launch_bounds__(256) cvt_hall_kernel()
{
    const size_t i = ((size_t)blockIdx.x * 256 + threadIdx.x) * 4;
    float4 v = *reinterpret_cast<const float4*>(g_hall + i);
    __nv_bfloat162* p = reinterpret_cast<__nv_bfloat162*>(g_hall_bf + i);
    p[0] = __floats2bfloat162_rn(v.x, v.y);
    p[1] = __floats2bfloat162_rn(v.z, v.w);
}

// ---------------- HMMA bf16 GEMM: logits[2048,32000] = hall @ out_w^T ----------
__global__ void __launch_bounds__(256)
logits_mma_kernel(const float* __restrict__ bias, float* __restrict__ C)
{
    __shared__ __align__(16) __nv_bfloat16 sA[128][72];   // 72 = 64 + 8 pad
    __shared__ __align__(16) __nv_bfloat16 sB[128][72];

    const int tid = threadIdx.x, warp = tid >> 5, lane = tid & 31;
    const int bm = blockIdx.x * 128;
    const int bn = blockIdx.y * 128;
    const int warp_m = (warp & 1) * 64;
    const int warp_n = (warp >> 1) * 32;

    float acc[4][4][4];
#pragma unroll
    for (int mt = 0; mt < 4; mt++)
#pragma unroll
        for (int nt = 0; nt < 4; nt++)
#pragma unroll
            for (int e = 0; e < 4; e++) acc[mt][nt][e] = 0.f;

    const __nv_bfloat16* A = g_hall_bf + (size_t)bm * Hh;
    const __nv_bfloat16* B = g_outw_bf + (size_t)bn * Hh;

    const uint32_t sa0 = smem_u32(sA);
    const uint32_t sb0 = smem_u32(sB);
    const uint32_t aaddr = sa0 + (uint32_t)(((warp_m + (lane & 15)) * 72 + (lane >> 4) * 8) * 2);
    const uint32_t baddr = sb0 + (uint32_t)(((warp_n + (lane & 7)) * 72 + ((lane >> 3) & 1) * 8) * 2);

    const int ldrow = tid >> 3, ldcu = tid & 7;

    for (int k0 = 0; k0 < Hh; k0 += 64) {
#pragma unroll
        for (int i = 0; i < 4; i++) {
            const int row = ldrow + i * 32;
            const size_t go = (size_t)row * Hh + k0 + ldcu * 8;
            *(uint4*)(&sA[row][ldcu * 8]) = *(const uint4*)(A + go);
            *(uint4*)(&sB[row][ldcu * 8]) = *(const uint4*)(B + go);
        }
        __syncthreads();

#pragma unroll
        for (int ks = 0; ks < 4; ks++) {
            uint32_t a[4][4], b[4][2];
#pragma unroll
            for (int mt = 0; mt < 4; mt++) {
                const uint32_t ad = aaddr + (uint32_t)((mt * 16 * 72 + ks * 16) * 2);
                asm volatile("ldmatrix.sync.aligned.m8n8.x4.shared.b16 {%0,%1,%2,%3}, [%4];"
                             : "=r"(a[mt][0]), "=r"(a[mt][1]), "=r"(a[mt][2]), "=r"(a[mt][3])
                             : "r"(ad));
            }
#pragma unroll
            for (int nt = 0; nt < 4; nt++) {
                const uint32_t bd = baddr + (uint32_t)((nt * 8 * 72 + ks * 16) * 2);
                asm volatile("ldmatrix.sync.aligned.m8n8.x2.shared.b16 {%0,%1}, [%2];"
                             : "=r"(b[nt][0]), "=r"(b[nt][1]) : "r"(bd));
            }
#pragma unroll
            for (int mt = 0; mt < 4; mt++)
#pragma unroll
                for (int nt = 0; nt < 4; nt++) {
                    asm volatile(
                        "mma.sync.aligned.m16n8k16.row.col.f32.bf16.bf16.f32 "
                        "{%0,%1,%2,%3}, {%4,%5,%6,%7}, {%8,%9}, {%0,%1,%2,%3};"
                        : "+f"(acc[mt][nt][0]), "+f"(acc[mt][nt][1]),
                          "+f"(acc[mt][nt][2]), "+f"(acc[mt][nt][3])
                        : "r"(a[mt][0]), "r"(a[mt][1]), "r"(a[mt][2]), "r"(a[mt][3]),
                          "r"(b[nt][0]), "r"(b[nt][1]));
                }
        }
        __syncthreads();
    }

    const int g = lane >> 2, q = lane & 3;
#pragma unroll
    for (int mt = 0; mt < 4; mt++) {
        const int r0 = bm + warp_m + mt * 16 + g;
#pragma unroll
        for (int nt = 0; nt < 4; nt++) {
            const int col = bn + warp_n + nt * 8 + q * 2;
            const float2 bv = *(const float2*)(bias + col);
            float2 o0, o1;
            o0.x = acc[mt][nt][0] + bv.x; o0.y = acc[mt][nt][1] + bv.y;
            o1.x = acc[mt][nt][2] + bv.x; o1.y = acc[mt][nt][3] + bv.y;
            *(float2*)(C + (size_t)r0 * Vv + col)       = o0;
            *(float2*)(C + (size_t)(r0 + 8) * Vv + col) = o1;
        }
    }
}

// ---------------- log_softmax, 512 threads + float4 ----------------------------
__global__ void __launch_bounds__(512) lsm_kernel(float* __restrict__ p0)
{
    float* p = p0 + (size_t)blockIdx.x * Vv;
    const int tid = threadIdx.x;
    __shared__ float red[16];
    __shared__ float bcast;

    float m = -1e30f;
    for (int i = tid; i < Vv / 4; i += 512) {
        float4 v = ((const float4*)p)[i];
        m = fmaxf(m, fmaxf(fmaxf(v.x, v.y), fmaxf(v.z, v.w)));
    }
#pragma unroll
    for (int o = 16; o > 0; o >>= 1) m = fmaxf(m, __shfl_xor_sync(0xffffffffu, m, o));
    if ((tid & 31) == 0) red[tid >> 5] = m;
    __syncthreads();
    if (tid == 0) {
        float mm = red[0];
        for (int w = 1; w < 16; w++) mm = fmaxf(mm, red[w]);
        bcast = mm;
    }
    __syncthreads();
    const float M = bcast;

    float sum = 0.f;
    for (int i = tid; i < Vv / 4; i += 512) {
        float4 v = ((const float4*)p)[i];
        sum += expf(v.x - M) + expf(v.y - M) + expf(v.z - M) + expf(v.w - M);
    }
#pragma unroll
    for (int o = 16; o > 0; o >>= 1) sum += __shfl_xor_sync(0xffffffffu, sum, o);
    __syncthreads();
    if ((tid & 31) == 0) red[tid >> 5] = sum;
    __syncthreads();
    if (tid == 0) {
        float ss = 0.f;
        for (int w = 0; w < 16; w++) ss += red[w];
        bcast = M + logf(ss);
    }
    __syncthreads();
    const float lse = bcast;
    for (int i = tid; i < Vv / 4; i += 512) {
        float4 v = ((const float4*)p)[i];
        v.x -= lse; v.y -= lse; v.z -= lse; v.w -= lse;
        ((float4*)p)[i] = v;
    }
}

__global__ void copy_ht_kernel(float* __restrict__ hT)
{
    const int i = blockIdx.x * 256 + threadIdx.x;
    hT[i] = g_h[i];
}

// ---------------- launch --------------------------------------------------------
extern "C" void kernel_launch(void* const* d_in, const int* in_sizes, int n_in,
                              void* d_out, int out_size)
{
    const float* enc   = (const float*)d_in[0];
    const float* eh    = (const float*)d_in[1];
    const int*   tgt   = (const int*)  d_in[2];
    const float* emb   = (const float*)d_in[3];
    const float* Wa_w  = (const float*)d_in[4];
    const float* Wa_b  = (const float*)d_in[5];
    const float* Ua_w  = (const float*)d_in[6];
    const float* Ua_b  = (const float*)d_in[7];
    const float* Va_w  = (const float*)d_in[8];
    const float* Va_b  = (const float*)d_in[9];
    const float* W_ih  = (const float*)d_in[10];
    const float* W_hh  = (const float*)d_in[11];
    const float* b_ih  = (const float*)d_in[12];
    const float* b_hh  = (const float*)d_in[13];
    const float* out_w = (const float*)d_in[14];
    const float* out_b = (const float*)d_in[15];

    float* out    = (float*)d_out;
    float* logits = out;
    float* hT     = out + (size_t)Mtot * Vv;
    float* attn   = hT + (size_t)Bsz * Hh;

    init_h_kernel<<<Bsz * Hh / 256, 256>>>(eh);
    cvt_outw_kernel<<<(int)(((size_t)Vv * Hh / 4) / 256), 256>>>(out_w);
    ua_gemm_kernel<<<dim3((Bsz * Tt) / 128, Hh / 128), 256>>>(enc, Ua_w, Ua_b);

    for (int s = 0; s < BLK; s++) {
        qgh3_kernel<<<dim3(64, 4, 2), 256>>>(Wa_w, Wa_b, W_hh, b_hh);
        attn2_kernel<<<Bsz, 1024>>>(Va_w, Va_b, enc, attn, s);
        gi3_kernel<<<dim3(48, 4, 2), 256>>>(emb, tgt, W_ih, b_ih, s);
        gate_kernel<<<Bsz * Hh / 256, 256>>>(s);
    }

    cvt_hall_kernel<<<(Mtot * Hh / 4) / 256, 256>>>();
    logits_mma_kernel<<<dim3(Mtot / 128, Vv / 128), 256>>>(out_b, logits);
    lsm_kernel<<<Mtot, 512>>>(logits);
    copy_ht_kernel<<<Bsz * Hh / 256, 256>>>(hT);
}